// round 16
// baseline (speedup 1.0000x reference)
#include <cuda_runtime.h>
#include <math.h>

#define BATCH 8
#define FEAT 512
#define NUM 512
#define KK 32
#define NBLK 256      // all co-resident at occ 2 (148 SMs)

typedef unsigned long long ull;

// 1/sqrt(512): global L2 scale is exact (512 unit-norm rows per half)
#define GSC 0.04419417382415922f

// ---- dynamic smem layout (bytes) -------------------------------------------
// P1: W resident 4 chunks [32][129]        @      0 .. 66048
//     X double buffer 2 x [128][16]        @  66048 .. 82432
//     red_f [8][32][17]                    @  82432 .. 99840
//     asr   [8][33]                        @  99840 .. 100896
// P2 (time-separated overlays):
//     At  [32][514 floats]  (k-major A^T)  @      0 .. 65792
//     Xs  [16][516 floats]                 @  65792 .. 98816
//     fbuf[8 warps][1056 floats]  (fold)   @      0 .. 33792 (post-compute)
#define SMEM_BYTES 100896

// ---------------- device scratch (static, allocation-free) ----------------
__device__ float g_a[BATCH * NUM * KK];      // a[b][n][k]
__device__ float g_axp[BATCH * FEAT * KK];   // FINAL ax  [b][f][k] (no splits)
__device__ float g_ax2p[BATCH * FEAT * KK];  // FINAL ax2 [b][f][k]
__device__ float g_asumt[BATCH * KK * 32];   // asum partials [b][k][tile]
__device__ unsigned g_cnt = 0;               // barrier counter (self-resets)
__device__ unsigned g_gen = 0;               // barrier generation (monotonic)

__device__ __forceinline__ float wsum(float v) {
#pragma unroll
    for (int o = 16; o; o >>= 1) v += __shfl_xor_sync(0xffffffffu, v, o);
    return v;
}
__device__ __forceinline__ float wmax(float v) {
#pragma unroll
    for (int o = 16; o; o >>= 1) v = fmaxf(v, __shfl_xor_sync(0xffffffffu, v, o));
    return v;
}

// packed f32x2 helpers (sm_100+)
__device__ __forceinline__ ull pk(float lo, float hi) {
    ull r;
    asm("mov.b64 %0, {%1, %2};" : "=l"(r) : "f"(lo), "f"(hi));
    return r;
}
__device__ __forceinline__ void upk(float& lo, float& hi, ull v) {
    asm("mov.b64 {%0, %1}, %2;" : "=f"(lo), "=f"(hi) : "l"(v));
}
__device__ __forceinline__ void ffma2(ull& d, ull a, ull b) {
    asm("fma.rn.f32x2 %0, %1, %2, %0;" : "+l"(d) : "l"(a), "l"(b));
}
__device__ __forceinline__ ull fmul2(ull a, ull b) {
    ull r;
    asm("mul.rn.f32x2 %0, %1, %2;" : "=l"(r) : "l"(a), "l"(b));
    return r;
}
__device__ __forceinline__ float foldu(ull v) {
    float lo, hi;
    upk(lo, hi, v);
    return lo + hi;
}

// Replay-safe grid barrier (volatile-load polling, monotonic generation).
__device__ __forceinline__ void gridbar() {
    __syncthreads();
    if (threadIdx.x == 0) {
        __threadfence();
        unsigned gen = *((volatile unsigned*)&g_gen);
        if (atomicAdd(&g_cnt, 1u) == NBLK - 1u) {
            *((volatile unsigned*)&g_cnt) = 0u;
            __threadfence();
            atomicAdd(&g_gen, 1u);
        } else {
            while (*((volatile unsigned*)&g_gen) == gen) __nanosleep(64);
        }
        __threadfence();
    }
    __syncthreads();
}

// ---------------- single kernel: softmax -> bar -> gemm -> bar -> fv ---------
__global__ __launch_bounds__(256, 2) void k_all(const float* __restrict__ x,
                                                const float* __restrict__ W,
                                                const float* __restrict__ bias,
                                                const float* __restrict__ mu,
                                                const float* __restrict__ sigma,
                                                float* __restrict__ out) {
    extern __shared__ __align__(16) char smx[];
    float* Wf   = reinterpret_cast<float*>(smx);          // [4 chunks][32][129]
    float* X4   = Wf + 16512;                             // 2 x [128][16]
    float* redf = Wf + 20608;                             // [8][32][17]
    float* asr  = Wf + 24960;                             // [8][33]

    const int tid  = threadIdx.x;
    const int w    = tid >> 5;
    const int lane = tid & 31;
    const int bx   = blockIdx.x;

    // phase-2 unit: b2 = bx>>5, 16-f tile ft2 = bx&31
    const int b2 = bx >> 5;
    const int f02 = (bx & 31) * 16;

    // ================= PHASE 1: logits + softmax + asum (r15 verbatim) =======
    {
        const int b    = bx >> 5;
        const int tile = bx & 31;
        const int n0   = tile * 16;

        // stage ALL W once: coalesced LDG, conflict-free STS
#pragma unroll
        for (int i = 0; i < 64; i++) {
            int idx = tid + i * 256;
            int k = idx >> 9, f = idx & 511;
            Wf[(f >> 7) * 4128 + k * 129 + (f & 127)] = W[k * FEAT + f];
        }
        // stage X chunk 0 into buffer 0
#pragma unroll
        for (int i = 0; i < 2; i++) {
            int idx = tid + i * 256;
            int fr = idx >> 2, c4 = (idx & 3) * 4;
            float4 v = *reinterpret_cast<const float4*>(
                &x[((size_t)b * FEAT + fr) * NUM + n0 + c4]);
            *reinterpret_cast<float4*>(&X4[fr * 16 + c4]) = v;
        }

        ull acc[8] = {0, 0, 0, 0, 0, 0, 0, 0};

        for (int t = 0; t < 4; t++) {
            __syncthreads();
            if (t < 3) {
                const int fb = (t + 1) * 128;
                float* xb = &X4[((t + 1) & 1) * 2048];
#pragma unroll
                for (int i = 0; i < 2; i++) {
                    int idx = tid + i * 256;
                    int fr = idx >> 2, c4 = (idx & 3) * 4;
                    float4 v = *reinterpret_cast<const float4*>(
                        &x[((size_t)b * FEAT + fb + fr) * NUM + n0 + c4]);
                    *reinterpret_cast<float4*>(&xb[fr * 16 + c4]) = v;
                }
            }
            const float* wc = &Wf[t * 4128 + lane * 129];
            const float* xc = &X4[(t & 1) * 2048];
            const int fw = w * 16;
#pragma unroll 4
            for (int fi = 0; fi < 16; fi++) {
                const int fl = fw + fi;
                float wv = wc[fl];                                // LDS32 cf
                ull   wp = pk(wv, wv);
                const ulonglong2* xr = reinterpret_cast<const ulonglong2*>(&xc[fl * 16]);
                ulonglong2 xa = xr[0];                            // LDS128 bc
                ulonglong2 xb = xr[1];
                ffma2(acc[0], wp, xa.x);
                ffma2(acc[1], wp, xa.y);
                ffma2(acc[2], wp, xb.x);
                ffma2(acc[3], wp, xb.y);
                xa = xr[2];
                xb = xr[3];
                ffma2(acc[4], wp, xa.x);
                ffma2(acc[5], wp, xa.y);
                ffma2(acc[6], wp, xb.x);
                ffma2(acc[7], wp, xb.y);
            }
        }

        __syncthreads();
        {
            float* r = &redf[(w * 32 + lane) * 17];
#pragma unroll
            for (int j = 0; j < 8; j++) {
                float f0, f1;
                upk(f0, f1, acc[j]);
                r[2 * j]     = f0;
                r[2 * j + 1] = f1;
            }
        }
        __syncthreads();

        {
            float l0 = 0.f, l1 = 0.f;
#pragma unroll
            for (int g = 0; g < 8; g++) {
                const float* r = &redf[(g * 32 + lane) * 17 + 2 * w];
                l0 += r[0];
                l1 += r[1];
            }
            const float bv = bias[lane];
            float pa;
            {
                float lg = l0 + bv;
                float m = wmax(lg);
                float e = __expf(lg - m);
                float s = wsum(e);
                float a = e / s;
                g_a[((size_t)b * NUM + n0 + 2 * w) * KK + lane] = a;
                pa = a;
            }
            {
                float lg = l1 + bv;
                float m = wmax(lg);
                float e = __expf(lg - m);
                float s = wsum(e);
                float a = e / s;
                g_a[((size_t)b * NUM + n0 + 2 * w + 1) * KK + lane] = a;
                pa += a;
            }
            asr[w * 33 + lane] = pa;
        }
        __syncthreads();
        if (tid < 32) {
            float s = 0.f;
#pragma unroll
            for (int g = 0; g < 8; g++) s += asr[g * 33 + tid];
            g_asumt[((size_t)b * KK + tid) * 32 + tile] = s;
        }
        __syncthreads();   // all P1 smem reads done before Xs overlay
    }

    // pre-barrier: stage X tile [16 f][512 n] (input-only; overlays dead P1 smem)
    {
        float* Xsf = reinterpret_cast<float*>(smx + 65792);   // stride 516
#pragma unroll
        for (int i = 0; i < 8; i++) {
            int idx = tid + i * 256;
            int fr = idx >> 7, n4 = (idx & 127) * 4;
            float4 v = *reinterpret_cast<const float4*>(
                &x[((size_t)b2 * FEAT + f02 + fr) * NUM + n4]);
            *reinterpret_cast<float4*>(&Xsf[fr * 516 + n4]) = v;
        }
    }

    gridbar();

    // ================= PHASE 2: full-n GEMM, 1 unit/CTA, NO global partials ===
    // warp w reduces n in [64w, 64w+64). lane: fg = lane>>3, kg = lane&7.
    // thread tile: f = f02 + fg + 4j (j<4), k = kg + 8m (m<4).
    {
        const int fg = lane >> 3;
        const int kg = lane & 7;

        // stage A^T [32 k][512 n] from g_a (coalesced LDG.128; scalar STS)
        float* Atf = reinterpret_cast<float*>(smx);           // stride 514
#pragma unroll
        for (int i = 0; i < 16; i++) {
            int idx = tid + i * 256;
            int kq = idx & 7, n = idx >> 3;
            float4 v = *reinterpret_cast<const float4*>(
                &g_a[((size_t)b2 * NUM + n) * KK + kq * 4]);
            Atf[(kq * 4 + 0) * 514 + n] = v.x;
            Atf[(kq * 4 + 1) * 514 + n] = v.y;
            Atf[(kq * 4 + 2) * 514 + n] = v.z;
            Atf[(kq * 4 + 3) * 514 + n] = v.w;
        }
        __syncthreads();

        ull ac1[4][4], ac2[4][4];
#pragma unroll
        for (int j = 0; j < 4; j++)
#pragma unroll
            for (int m = 0; m < 4; m++) { ac1[j][m] = 0ULL; ac2[j][m] = 0ULL; }

        const ull* Au = reinterpret_cast<const ull*>(smx);            // stride 257
        const ull* Xu = reinterpret_cast<const ull*>(smx + 65792);    // stride 258
        const int npb = w * 32;
        const ull* Xr = &Xu[(size_t)fg * 258 + npb];
        const ull* Ar = &Au[(size_t)kg * 257 + npb];

#pragma unroll 4
        for (int np = 0; np < 32; np++) {
            ull x0 = Xr[np];                  // f = fg      (LDS64 cf, bcast x8)
            ull x1 = Xr[np + 4 * 258];        // f = fg+4
            ull x2 = Xr[np + 8 * 258];        // f = fg+8
            ull x3 = Xr[np + 12 * 258];       // f = fg+12
            ull a0 = Ar[np];                  // k = kg      (LDS64 cf, bcast x4)
            ull a1 = Ar[np + 8 * 257];        // k = kg+8
            ull a2 = Ar[np + 16 * 257];       // k = kg+16
            ull a3 = Ar[np + 24 * 257];       // k = kg+24
            ull q0 = fmul2(x0, x0);
            ull q1 = fmul2(x1, x1);
            ull q2 = fmul2(x2, x2);
            ull q3 = fmul2(x3, x3);
            ffma2(ac1[0][0], a0, x0);  ffma2(ac2[0][0], a0, q0);
            ffma2(ac1[0][1], a1, x0);  ffma2(ac2[0][1], a1, q0);
            ffma2(ac1[0][2], a2, x0);  ffma2(ac2[0][2], a2, q0);
            ffma2(ac1[0][3], a3, x0);  ffma2(ac2[0][3], a3, q0);
            ffma2(ac1[1][0], a0, x1);  ffma2(ac2[1][0], a0, q1);
            ffma2(ac1[1][1], a1, x1);  ffma2(ac2[1][1], a1, q1);
            ffma2(ac1[1][2], a2, x1);  ffma2(ac2[1][2], a2, q1);
            ffma2(ac1[1][3], a3, x1);  ffma2(ac2[1][3], a3, q1);
            ffma2(ac1[2][0], a0, x2);  ffma2(ac2[2][0], a0, q2);
            ffma2(ac1[2][1], a1, x2);  ffma2(ac2[2][1], a1, q2);
            ffma2(ac1[2][2], a2, x2);  ffma2(ac2[2][2], a2, q2);
            ffma2(ac1[2][3], a3, x2);  ffma2(ac2[2][3], a3, q2);
            ffma2(ac1[3][0], a0, x3);  ffma2(ac2[3][0], a0, q3);
            ffma2(ac1[3][1], a1, x3);  ffma2(ac2[3][1], a1, q3);
            ffma2(ac1[3][2], a2, x3);  ffma2(ac2[3][2], a2, q3);
            ffma2(ac1[3][3], a3, x3);  ffma2(ac2[3][3], a3, q3);
        }
        __syncthreads();   // At dead; fold buffer overlays it

        // per-warp fold write: fbuf[w][lane][v], stride 33 -> conflict-free
        float* fbuf = reinterpret_cast<float*>(smx);
        {
            float* fr = &fbuf[(w * 32 + lane) * 33];
#pragma unroll
            for (int j = 0; j < 4; j++)
#pragma unroll
                for (int m = 0; m < 4; m++) {
                    fr[j * 8 + m * 2]     = foldu(ac1[j][m]);
                    fr[j * 8 + m * 2 + 1] = foldu(ac2[j][m]);
                }
        }
        __syncthreads();

        // cross-warp reduce + FINAL store: thread = (f = tid>>4, kq = (tid>>1)&7, t = tid&1)
        {
            const int f  = tid >> 4;
            const int kq = (tid >> 1) & 7;
            const int t  = tid & 1;
            float vv[4];
#pragma unroll
            for (int i = 0; i < 4; i++) {
                const int k = kq * 4 + i;
                const int L = (f & 3) * 8 + (k & 7);
                const int V = (f >> 2) * 8 + (k >> 3) * 2 + t;
                float s = 0.f;
#pragma unroll
                for (int g = 0; g < 8; g++) s += fbuf[(g * 32 + L) * 33 + V];
                vv[i] = s;
            }
            const size_t base = ((size_t)b2 * FEAT + f02 + f) * KK + kq * 4;
            float4 o4 = make_float4(vv[0], vv[1], vv[2], vv[3]);
            if (t == 0) *reinterpret_cast<float4*>(&g_axp[base])  = o4;
            else        *reinterpret_cast<float4*>(&g_ax2p[base]) = o4;
        }
    }

    gridbar();

    // ================= PHASE 3: fisher vectors + rownorm + const scale ========
    {
        const int b      = bx >> 5;
        const int fgbase = (bx & 31) * 2;

        // asum[b][k]: 32 contiguous partials -> 8x LDG.128
        float asv = 0.f;
        {
            const float4* p = reinterpret_cast<const float4*>(&g_asumt[((size_t)b * KK + lane) * 32]);
#pragma unroll
            for (int q = 0; q < 8; q++) {
                float4 v = p[q];
                asv += (v.x + v.y) + (v.z + v.w);
            }
        }

#pragma unroll
        for (int j = 0; j < 2; j++) {
            const int f = (fgbase + j) * 8 + w;
            const size_t po = ((size_t)b * FEAT + f) * KK + lane;
            float ax  = g_axp[po];     // single final load (no split loop)
            float ax2 = g_ax2p[po];
            float muv = mu[f * KK + lane];
            float sg  = sigma[f * KK + lane];
            float fv1 = (ax - muv * asv) / sg;
            float fv2 = (ax2 - 2.f * muv * ax + muv * muv * asv) / (sg * sg) - asv;

            float n1 = sqrtf(wsum(fv1 * fv1));
            float n2 = sqrtf(wsum(fv2 * fv2));
            float v1 = fv1 / fmaxf(n1, 1e-12f) * GSC;
            float v2 = fv2 / fmaxf(n2, 1e-12f) * GSC;

            const size_t ob = (size_t)b * 2 * FEAT * KK;
            out[ob + (size_t)f * KK + lane]             = v1;
            out[ob + FEAT * KK + (size_t)f * KK + lane] = v2;
        }
    }
}

// ---------------- launch -----------------------------------------------------
extern "C" void kernel_launch(void* const* d_in, const int* in_sizes, int n_in,
                              void* d_out, int out_size) {
    (void)in_sizes; (void)n_in; (void)out_size;
    const float* x     = (const float*)d_in[0];
    const float* W     = (const float*)d_in[1];
    const float* bias  = (const float*)d_in[2];
    const float* mu    = (const float*)d_in[3];
    const float* sigma = (const float*)d_in[4];
    float* out = (float*)d_out;

    cudaFuncSetAttribute(k_all, cudaFuncAttributeMaxDynamicSharedMemorySize,
                         SMEM_BYTES);
    k_all<<<NBLK, 256, SMEM_BYTES>>>(x, W, bias, mu, sigma, out);
}

// round 17
// speedup vs baseline: 1.0114x; 1.0114x over previous
#include <cuda_runtime.h>
#include <math.h>

#define BATCH 8
#define FEAT 512
#define NUM 512
#define KK 32
#define NBLK 256      // all co-resident at occ 2 (148 SMs)
#define NGRP 32       // CTAs per batch group (barrier scope)

typedef unsigned long long ull;

// 1/sqrt(512): global L2 scale is exact (512 unit-norm rows per half)
#define GSC 0.04419417382415922f

// ---- dynamic smem layout (bytes) -------------------------------------------
#define SMEM_BYTES 100896

// ---------------- device scratch (static, allocation-free) ----------------
__device__ float g_a[BATCH * NUM * KK];      // a[b][n][k]
__device__ float g_axp[BATCH * FEAT * KK];   // FINAL ax  [b][f][k]
__device__ float g_ax2p[BATCH * FEAT * KK];  // FINAL ax2 [b][f][k]
__device__ float g_asumt[BATCH * KK * 32];   // asum partials [b][k][tile]
__device__ unsigned g_cntb[BATCH];           // per-batch barrier counters (self-reset)
__device__ unsigned g_genb[BATCH];           // per-batch generations (monotonic)

__device__ __forceinline__ float wsum(float v) {
#pragma unroll
    for (int o = 16; o; o >>= 1) v += __shfl_xor_sync(0xffffffffu, v, o);
    return v;
}
__device__ __forceinline__ float wmax(float v) {
#pragma unroll
    for (int o = 16; o; o >>= 1) v = fmaxf(v, __shfl_xor_sync(0xffffffffu, v, o));
    return v;
}

// packed f32x2 helpers (sm_100+)
__device__ __forceinline__ ull pk(float lo, float hi) {
    ull r;
    asm("mov.b64 %0, {%1, %2};" : "=l"(r) : "f"(lo), "f"(hi));
    return r;
}
__device__ __forceinline__ void upk(float& lo, float& hi, ull v) {
    asm("mov.b64 {%0, %1}, %2;" : "=f"(lo), "=f"(hi) : "l"(v));
}
__device__ __forceinline__ void ffma2(ull& d, ull a, ull b) {
    asm("fma.rn.f32x2 %0, %1, %2, %0;" : "+l"(d) : "l"(a), "l"(b));
}
__device__ __forceinline__ ull fmul2(ull a, ull b) {
    ull r;
    asm("mul.rn.f32x2 %0, %1, %2;" : "=l"(r) : "l"(a), "l"(b));
    return r;
}
__device__ __forceinline__ float foldu(ull v) {
    float lo, hi;
    upk(lo, hi, v);
    return lo + hi;
}

// Replay-safe PER-BATCH barrier: only the 32 CTAs of one batch synchronize.
// Different batches proceed independently -> cross-CTA spread decouples.
__device__ __forceinline__ void groupbar(int b) {
    __syncthreads();
    if (threadIdx.x == 0) {
        __threadfence();
        unsigned gen = *((volatile unsigned*)&g_genb[b]);
        if (atomicAdd(&g_cntb[b], 1u) == NGRP - 1u) {
            *((volatile unsigned*)&g_cntb[b]) = 0u;
            __threadfence();
            atomicAdd(&g_genb[b], 1u);
        } else {
            while (*((volatile unsigned*)&g_genb[b]) == gen) __nanosleep(64);
        }
        __threadfence();
    }
    __syncthreads();
}

// ---------------- single kernel: softmax -> bar(b) -> gemm -> bar(b) -> fv ---
__global__ __launch_bounds__(256, 2) void k_all(const float* __restrict__ x,
                                                const float* __restrict__ W,
                                                const float* __restrict__ bias,
                                                const float* __restrict__ mu,
                                                const float* __restrict__ sigma,
                                                float* __restrict__ out) {
    extern __shared__ __align__(16) char smx[];
    float* Wf   = reinterpret_cast<float*>(smx);          // [4 chunks][32][129]
    float* X4   = Wf + 16512;                             // 2 x [128][16]
    float* redf = Wf + 20608;                             // [8][32][17]
    float* asr  = Wf + 24960;                             // [8][33]

    const int tid  = threadIdx.x;
    const int w    = tid >> 5;
    const int lane = tid & 31;
    const int bx   = blockIdx.x;

    const int bgrp = bx >> 5;         // batch group (phases 1,2,3 all use it)
    const int f02  = (bx & 31) * 16;  // phase-2 16-f tile

    // ================= PHASE 1: logits + softmax + asum =======================
    {
        const int b    = bgrp;
        const int tile = bx & 31;
        const int n0   = tile * 16;

        // stage ALL W once: LDG.128 (16/thread), conflict-free scalar STS
#pragma unroll
        for (int i = 0; i < 16; i++) {
            int idx = tid + i * 256;
            int k = idx >> 7, f4 = (idx & 127) * 4;
            float4 v = *reinterpret_cast<const float4*>(&W[k * FEAT + f4]);
            float* d = &Wf[(f4 >> 7) * 4128 + k * 129 + (f4 & 127)];
            d[0] = v.x; d[1] = v.y; d[2] = v.z; d[3] = v.w;
        }
        // stage X chunk 0 into buffer 0
#pragma unroll
        for (int i = 0; i < 2; i++) {
            int idx = tid + i * 256;
            int fr = idx >> 2, c4 = (idx & 3) * 4;
            float4 v = *reinterpret_cast<const float4*>(
                &x[((size_t)b * FEAT + fr) * NUM + n0 + c4]);
            *reinterpret_cast<float4*>(&X4[fr * 16 + c4]) = v;
        }

        ull acc[8] = {0, 0, 0, 0, 0, 0, 0, 0};

        for (int t = 0; t < 4; t++) {
            __syncthreads();
            if (t < 3) {
                const int fb = (t + 1) * 128;
                float* xb = &X4[((t + 1) & 1) * 2048];
#pragma unroll
                for (int i = 0; i < 2; i++) {
                    int idx = tid + i * 256;
                    int fr = idx >> 2, c4 = (idx & 3) * 4;
                    float4 v = *reinterpret_cast<const float4*>(
                        &x[((size_t)b * FEAT + fb + fr) * NUM + n0 + c4]);
                    *reinterpret_cast<float4*>(&xb[fr * 16 + c4]) = v;
                }
            }
            const float* wc = &Wf[t * 4128 + lane * 129];
            const float* xc = &X4[(t & 1) * 2048];
            const int fw = w * 16;
#pragma unroll 4
            for (int fi = 0; fi < 16; fi++) {
                const int fl = fw + fi;
                float wv = wc[fl];                                // LDS32 cf
                ull   wp = pk(wv, wv);
                const ulonglong2* xr = reinterpret_cast<const ulonglong2*>(&xc[fl * 16]);
                ulonglong2 xa = xr[0];                            // LDS128 bc
                ulonglong2 xb = xr[1];
                ffma2(acc[0], wp, xa.x);
                ffma2(acc[1], wp, xa.y);
                ffma2(acc[2], wp, xb.x);
                ffma2(acc[3], wp, xb.y);
                xa = xr[2];
                xb = xr[3];
                ffma2(acc[4], wp, xa.x);
                ffma2(acc[5], wp, xa.y);
                ffma2(acc[6], wp, xb.x);
                ffma2(acc[7], wp, xb.y);
            }
        }

        __syncthreads();
        {
            float* r = &redf[(w * 32 + lane) * 17];
#pragma unroll
            for (int j = 0; j < 8; j++) {
                float f0, f1;
                upk(f0, f1, acc[j]);
                r[2 * j]     = f0;
                r[2 * j + 1] = f1;
            }
        }
        __syncthreads();

        {
            float l0 = 0.f, l1 = 0.f;
#pragma unroll
            for (int g = 0; g < 8; g++) {
                const float* r = &redf[(g * 32 + lane) * 17 + 2 * w];
                l0 += r[0];
                l1 += r[1];
            }
            const float bv = bias[lane];
            float pa;
            {
                float lg = l0 + bv;
                float m = wmax(lg);
                float e = __expf(lg - m);
                float s = wsum(e);
                float a = e / s;
                g_a[((size_t)b * NUM + n0 + 2 * w) * KK + lane] = a;
                pa = a;
            }
            {
                float lg = l1 + bv;
                float m = wmax(lg);
                float e = __expf(lg - m);
                float s = wsum(e);
                float a = e / s;
                g_a[((size_t)b * NUM + n0 + 2 * w + 1) * KK + lane] = a;
                pa += a;
            }
            asr[w * 33 + lane] = pa;
        }
        __syncthreads();
        if (tid < 32) {
            float s = 0.f;
#pragma unroll
            for (int g = 0; g < 8; g++) s += asr[g * 33 + tid];
            g_asumt[((size_t)b * KK + tid) * 32 + tile] = s;
        }
        __syncthreads();   // all P1 smem reads done before Xs overlay
    }

    // pre-barrier: stage X tile [16 f][512 n] (input-only; overlays dead P1 smem)
    {
        float* Xsf = reinterpret_cast<float*>(smx + 65792);   // stride 516
#pragma unroll
        for (int i = 0; i < 8; i++) {
            int idx = tid + i * 256;
            int fr = idx >> 7, n4 = (idx & 127) * 4;
            float4 v = *reinterpret_cast<const float4*>(
                &x[((size_t)bgrp * FEAT + f02 + fr) * NUM + n4]);
            *reinterpret_cast<float4*>(&Xsf[fr * 516 + n4]) = v;
        }
    }

    groupbar(bgrp);   // only this batch's 32 producers/consumers sync

    // ================= PHASE 2: full-n GEMM, 1 unit/CTA, NO global partials ===
    {
        const int fg = lane >> 3;
        const int kg = lane & 7;

        // stage A^T [32 k][512 n] from g_a (coalesced LDG.128; scalar STS)
        float* Atf = reinterpret_cast<float*>(smx);           // stride 514
#pragma unroll
        for (int i = 0; i < 16; i++) {
            int idx = tid + i * 256;
            int kq = idx & 7, n = idx >> 3;
            float4 v = *reinterpret_cast<const float4*>(
                &g_a[((size_t)bgrp * NUM + n) * KK + kq * 4]);
            Atf[(kq * 4 + 0) * 514 + n] = v.x;
            Atf[(kq * 4 + 1) * 514 + n] = v.y;
            Atf[(kq * 4 + 2) * 514 + n] = v.z;
            Atf[(kq * 4 + 3) * 514 + n] = v.w;
        }
        __syncthreads();

        ull ac1[4][4], ac2[4][4];
#pragma unroll
        for (int j = 0; j < 4; j++)
#pragma unroll
            for (int m = 0; m < 4; m++) { ac1[j][m] = 0ULL; ac2[j][m] = 0ULL; }

        const ull* Au = reinterpret_cast<const ull*>(smx);            // stride 257
        const ull* Xu = reinterpret_cast<const ull*>(smx + 65792);    // stride 258
        const int npb = w * 32;
        const ull* Xr = &Xu[(size_t)fg * 258 + npb];
        const ull* Ar = &Au[(size_t)kg * 257 + npb];

#pragma unroll 4
        for (int np = 0; np < 32; np++) {
            ull x0 = Xr[np];                  // f = fg      (LDS64 cf, bcast x8)
            ull x1 = Xr[np + 4 * 258];        // f = fg+4
            ull x2 = Xr[np + 8 * 258];        // f = fg+8
            ull x3 = Xr[np + 12 * 258];       // f = fg+12
            ull a0 = Ar[np];                  // k = kg      (LDS64 cf, bcast x4)
            ull a1 = Ar[np + 8 * 257];        // k = kg+8
            ull a2 = Ar[np + 16 * 257];       // k = kg+16
            ull a3 = Ar[np + 24 * 257];       // k = kg+24
            ull q0 = fmul2(x0, x0);
            ull q1 = fmul2(x1, x1);
            ull q2 = fmul2(x2, x2);
            ull q3 = fmul2(x3, x3);
            ffma2(ac1[0][0], a0, x0);  ffma2(ac2[0][0], a0, q0);
            ffma2(ac1[0][1], a1, x0);  ffma2(ac2[0][1], a1, q0);
            ffma2(ac1[0][2], a2, x0);  ffma2(ac2[0][2], a2, q0);
            ffma2(ac1[0][3], a3, x0);  ffma2(ac2[0][3], a3, q0);
            ffma2(ac1[1][0], a0, x1);  ffma2(ac2[1][0], a0, q1);
            ffma2(ac1[1][1], a1, x1);  ffma2(ac2[1][1], a1, q1);
            ffma2(ac1[1][2], a2, x1);  ffma2(ac2[1][2], a2, q1);
            ffma2(ac1[1][3], a3, x1);  ffma2(ac2[1][3], a3, q1);
            ffma2(ac1[2][0], a0, x2);  ffma2(ac2[2][0], a0, q2);
            ffma2(ac1[2][1], a1, x2);  ffma2(ac2[2][1], a1, q2);
            ffma2(ac1[2][2], a2, x2);  ffma2(ac2[2][2], a2, q2);
            ffma2(ac1[2][3], a3, x2);  ffma2(ac2[2][3], a3, q2);
            ffma2(ac1[3][0], a0, x3);  ffma2(ac2[3][0], a0, q3);
            ffma2(ac1[3][1], a1, x3);  ffma2(ac2[3][1], a1, q3);
            ffma2(ac1[3][2], a2, x3);  ffma2(ac2[3][2], a2, q3);
            ffma2(ac1[3][3], a3, x3);  ffma2(ac2[3][3], a3, q3);
        }
        __syncthreads();   // At dead; fold buffer overlays it

        // per-warp fold write: fbuf[w][lane][v], stride 33 -> conflict-free
        float* fbuf = reinterpret_cast<float*>(smx);
        {
            float* fr = &fbuf[(w * 32 + lane) * 33];
#pragma unroll
            for (int j = 0; j < 4; j++)
#pragma unroll
                for (int m = 0; m < 4; m++) {
                    fr[j * 8 + m * 2]     = foldu(ac1[j][m]);
                    fr[j * 8 + m * 2 + 1] = foldu(ac2[j][m]);
                }
        }
        __syncthreads();

        // cross-warp reduce + FINAL store
        {
            const int f  = tid >> 4;
            const int kq = (tid >> 1) & 7;
            const int t  = tid & 1;
            float vv[4];
#pragma unroll
            for (int i = 0; i < 4; i++) {
                const int k = kq * 4 + i;
                const int L = (f & 3) * 8 + (k & 7);
                const int V = (f >> 2) * 8 + (k >> 3) * 2 + t;
                float s = 0.f;
#pragma unroll
                for (int g = 0; g < 8; g++) s += fbuf[(g * 32 + L) * 33 + V];
                vv[i] = s;
            }
            const size_t base = ((size_t)bgrp * FEAT + f02 + f) * KK + kq * 4;
            float4 o4 = make_float4(vv[0], vv[1], vv[2], vv[3]);
            if (t == 0) *reinterpret_cast<float4*>(&g_axp[base])  = o4;
            else        *reinterpret_cast<float4*>(&g_ax2p[base]) = o4;
        }
    }

    groupbar(bgrp);

    // ================= PHASE 3: fisher vectors + rownorm + const scale ========
    {
        const int b      = bgrp;
        const int fgbase = (bx & 31) * 2;

        // asum[b][k]: 32 contiguous partials -> 8x LDG.128
        float asv = 0.f;
        {
            const float4* p = reinterpret_cast<const float4*>(&g_asumt[((size_t)b * KK + lane) * 32]);
#pragma unroll
            for (int q = 0; q < 8; q++) {
                float4 v = p[q];
                asv += (v.x + v.y) + (v.z + v.w);
            }
        }

#pragma unroll
        for (int j = 0; j < 2; j++) {
            const int f = (fgbase + j) * 8 + w;
            const size_t po = ((size_t)b * FEAT + f) * KK + lane;
            float ax  = g_axp[po];
            float ax2 = g_ax2p[po];
            float muv = mu[f * KK + lane];
            float sg  = sigma[f * KK + lane];
            float fv1 = (ax - muv * asv) / sg;
            float fv2 = (ax2 - 2.f * muv * ax + muv * muv * asv) / (sg * sg) - asv;

            float n1 = sqrtf(wsum(fv1 * fv1));
            float n2 = sqrtf(wsum(fv2 * fv2));
            float v1 = fv1 / fmaxf(n1, 1e-12f) * GSC;
            float v2 = fv2 / fmaxf(n2, 1e-12f) * GSC;

            const size_t ob = (size_t)b * 2 * FEAT * KK;
            out[ob + (size_t)f * KK + lane]             = v1;
            out[ob + FEAT * KK + (size_t)f * KK + lane] = v2;
        }
    }
}

// ---------------- launch -----------------------------------------------------
extern "C" void kernel_launch(void* const* d_in, const int* in_sizes, int n_in,
                              void* d_out, int out_size) {
    (void)in_sizes; (void)n_in; (void)out_size;
    const float* x     = (const float*)d_in[0];
    const float* W     = (const float*)d_in[1];
    const float* bias  = (const float*)d_in[2];
    const float* mu    = (const float*)d_in[3];
    const float* sigma = (const float*)d_in[4];
    float* out = (float*)d_out;

    cudaFuncSetAttribute(k_all, cudaFuncAttributeMaxDynamicSharedMemorySize,
                         SMEM_BYTES);
    k_all<<<NBLK, 256, SMEM_BYTES>>>(x, W, bias, mu, sigma, out);
}